// round 2
// baseline (speedup 1.0000x reference)
#include <cuda_runtime.h>

// Fused deterministic reduction (single kernel):
//   - grid-stride float4 dot-product partials -> g_partials[block]
//   - threadfence + ticket counter; last block reduces all partials in
//     fixed index order (deterministic) and writes -sum/B to out[0],
//     then resets the counter for graph-replay idempotence.

#define NBLOCKS 2048
#define NTHREADS 256

__device__ float g_partials[NBLOCKS];
__device__ unsigned int g_ticket = 0;

__global__ __launch_bounds__(NTHREADS) void dot_loss_kernel(
    const float4* __restrict__ fs, const float4* __restrict__ ft,
    float* __restrict__ out, int n4, float neg_inv_b) {
    float acc = 0.0f;
    int i = blockIdx.x * NTHREADS + threadIdx.x;
    const int stride = NBLOCKS * NTHREADS;

    // Unroll by 4, front-batched loads (MLP for the L1tex queue)
    #pragma unroll 1
    for (; i + 3 * stride < n4; i += 4 * stride) {
        float4 a0 = fs[i];
        float4 a1 = fs[i + stride];
        float4 a2 = fs[i + 2 * stride];
        float4 a3 = fs[i + 3 * stride];
        float4 b0 = ft[i];
        float4 b1 = ft[i + stride];
        float4 b2 = ft[i + 2 * stride];
        float4 b3 = ft[i + 3 * stride];
        acc = fmaf(a0.x, b0.x, acc); acc = fmaf(a0.y, b0.y, acc);
        acc = fmaf(a0.z, b0.z, acc); acc = fmaf(a0.w, b0.w, acc);
        acc = fmaf(a1.x, b1.x, acc); acc = fmaf(a1.y, b1.y, acc);
        acc = fmaf(a1.z, b1.z, acc); acc = fmaf(a1.w, b1.w, acc);
        acc = fmaf(a2.x, b2.x, acc); acc = fmaf(a2.y, b2.y, acc);
        acc = fmaf(a2.z, b2.z, acc); acc = fmaf(a2.w, b2.w, acc);
        acc = fmaf(a3.x, b3.x, acc); acc = fmaf(a3.y, b3.y, acc);
        acc = fmaf(a3.z, b3.z, acc); acc = fmaf(a3.w, b3.w, acc);
    }
    for (; i < n4; i += stride) {
        float4 a = fs[i];
        float4 b = ft[i];
        acc = fmaf(a.x, b.x, acc); acc = fmaf(a.y, b.y, acc);
        acc = fmaf(a.z, b.z, acc); acc = fmaf(a.w, b.w, acc);
    }

    // warp reduce
    #pragma unroll
    for (int off = 16; off > 0; off >>= 1)
        acc += __shfl_xor_sync(0xFFFFFFFFu, acc, off);

    __shared__ float s[NTHREADS / 32];
    __shared__ bool s_is_last;
    int lane = threadIdx.x & 31;
    int wid = threadIdx.x >> 5;
    if (lane == 0) s[wid] = acc;
    __syncthreads();

    if (wid == 0) {
        float v = (lane < NTHREADS / 32) ? s[lane] : 0.0f;
        #pragma unroll
        for (int off = 4; off > 0; off >>= 1)
            v += __shfl_xor_sync(0xFFFFFFFFu, v, off);
        if (lane == 0) {
            g_partials[blockIdx.x] = v;
            __threadfence();  // make partial visible before taking ticket
            unsigned int t = atomicAdd(&g_ticket, 1u);
            s_is_last = (t == NBLOCKS - 1);
        }
    }
    __syncthreads();

    if (s_is_last) {
        // This block sees all partials (fence + atomic ordering).
        // Fixed-order summation -> deterministic.
        float a2 = 0.0f;
        #pragma unroll
        for (int j = threadIdx.x; j < NBLOCKS; j += NTHREADS)
            a2 += g_partials[j];

        #pragma unroll
        for (int off = 16; off > 0; off >>= 1)
            a2 += __shfl_xor_sync(0xFFFFFFFFu, a2, off);

        if (lane == 0) s[wid] = a2;
        __syncthreads();

        if (wid == 0) {
            float v = (lane < NTHREADS / 32) ? s[lane] : 0.0f;
            #pragma unroll
            for (int off = 4; off > 0; off >>= 1)
                v += __shfl_xor_sync(0xFFFFFFFFu, v, off);
            if (lane == 0) {
                out[0] = v * neg_inv_b;
                g_ticket = 0;  // reset for next graph replay
            }
        }
    }
}

extern "C" void kernel_launch(void* const* d_in, const int* in_sizes, int n_in,
                              void* d_out, int out_size) {
    const float4* fs = (const float4*)d_in[0];
    const float4* ft = (const float4*)d_in[1];
    float* out = (float*)d_out;

    int n = in_sizes[0];   // B * D floats
    int n4 = n >> 2;       // float4 count

    int B = n / 512;       // D = 512
    float neg_inv_b = -1.0f / (float)B;

    dot_loss_kernel<<<NBLOCKS, NTHREADS>>>(fs, ft, out, n4, neg_inv_b);
}

// round 3
// speedup vs baseline: 1.0295x; 1.0295x over previous
#include <cuda_runtime.h>

// Single fused kernel, deterministic:
//   - grid-stride float4 dot-product partial per block
//   - block partial -> int64 fixed-point (x 2^40) -> atomicAdd into one cell
//     (integer adds are order-independent => bit-deterministic)
//   - ticket counter; last block reads the single total, writes -sum/B,
//     resets state for graph-replay idempotence.

#define NBLOCKS 2048
#define NTHREADS 256
#define FP_SCALE 1099511627776.0  // 2^40

__device__ unsigned long long g_sum = 0ull;
__device__ unsigned int g_ticket = 0;

__global__ __launch_bounds__(NTHREADS) void dot_loss_kernel(
    const float4* __restrict__ fs, const float4* __restrict__ ft,
    float* __restrict__ out, int n4, float neg_inv_b) {
    float acc = 0.0f;
    int i = blockIdx.x * NTHREADS + threadIdx.x;
    const int stride = NBLOCKS * NTHREADS;

    // Unroll by 4, front-batched streaming loads (MLP for the L1tex queue)
    #pragma unroll 1
    for (; i + 3 * stride < n4; i += 4 * stride) {
        float4 a0 = __ldcs(fs + i);
        float4 a1 = __ldcs(fs + i + stride);
        float4 a2 = __ldcs(fs + i + 2 * stride);
        float4 a3 = __ldcs(fs + i + 3 * stride);
        float4 b0 = __ldcs(ft + i);
        float4 b1 = __ldcs(ft + i + stride);
        float4 b2 = __ldcs(ft + i + 2 * stride);
        float4 b3 = __ldcs(ft + i + 3 * stride);
        acc = fmaf(a0.x, b0.x, acc); acc = fmaf(a0.y, b0.y, acc);
        acc = fmaf(a0.z, b0.z, acc); acc = fmaf(a0.w, b0.w, acc);
        acc = fmaf(a1.x, b1.x, acc); acc = fmaf(a1.y, b1.y, acc);
        acc = fmaf(a1.z, b1.z, acc); acc = fmaf(a1.w, b1.w, acc);
        acc = fmaf(a2.x, b2.x, acc); acc = fmaf(a2.y, b2.y, acc);
        acc = fmaf(a2.z, b2.z, acc); acc = fmaf(a2.w, b2.w, acc);
        acc = fmaf(a3.x, b3.x, acc); acc = fmaf(a3.y, b3.y, acc);
        acc = fmaf(a3.z, b3.z, acc); acc = fmaf(a3.w, b3.w, acc);
    }
    for (; i < n4; i += stride) {
        float4 a = __ldcs(fs + i);
        float4 b = __ldcs(ft + i);
        acc = fmaf(a.x, b.x, acc); acc = fmaf(a.y, b.y, acc);
        acc = fmaf(a.z, b.z, acc); acc = fmaf(a.w, b.w, acc);
    }

    // warp reduce
    #pragma unroll
    for (int off = 16; off > 0; off >>= 1)
        acc += __shfl_xor_sync(0xFFFFFFFFu, acc, off);

    __shared__ float s[NTHREADS / 32];
    int lane = threadIdx.x & 31;
    int wid = threadIdx.x >> 5;
    if (lane == 0) s[wid] = acc;
    __syncthreads();

    if (threadIdx.x == 0) {
        float v = 0.0f;
        #pragma unroll
        for (int w = 0; w < NTHREADS / 32; w++) v += s[w];

        // exact, order-independent accumulation: fixed-point int64
        long long fp = (long long)((double)v * FP_SCALE);
        atomicAdd(&g_sum, (unsigned long long)fp);
        __threadfence();
        unsigned int t = atomicAdd(&g_ticket, 1u);
        if (t == NBLOCKS - 1) {
            // all partials are in g_sum (fence + atomic ordering)
            unsigned long long total_u = atomicAdd(&g_sum, 0ull);  // atomic read
            long long total = (long long)total_u;
            double sum = (double)total * (1.0 / FP_SCALE);
            out[0] = (float)(sum * (double)neg_inv_b);
            // reset for next graph replay
            g_sum = 0ull;
            g_ticket = 0;
            __threadfence();
        }
    }
}

extern "C" void kernel_launch(void* const* d_in, const int* in_sizes, int n_in,
                              void* d_out, int out_size) {
    const float4* fs = (const float4*)d_in[0];
    const float4* ft = (const float4*)d_in[1];
    float* out = (float*)d_out;

    int n = in_sizes[0];   // B * D floats
    int n4 = n >> 2;       // float4 count

    int B = n / 512;       // D = 512
    float neg_inv_b = -1.0f / (float)B;

    dot_loss_kernel<<<NBLOCKS, NTHREADS>>>(fs, ft, out, n4, neg_inv_b);
}

// round 4
// speedup vs baseline: 1.0787x; 1.0478x over previous
#include <cuda_runtime.h>

// Single fused kernel, deterministic, 256-bit streaming loads (sm_100+).
//   - grid-stride float8 (LDG.E.256) dot-product partial per block
//   - block partial -> int64 fixed-point (x 2^40) -> atomicAdd (order-
//     independent integer adds => bit-deterministic)
//   - ticket counter; last block writes -sum/B and resets state.

#define NBLOCKS 2048
#define NTHREADS 256
#define FP_SCALE 1099511627776.0  // 2^40

__device__ unsigned long long g_sum = 0ull;
__device__ unsigned int g_ticket = 0;

__device__ __forceinline__ void ldg256_cs(const float* __restrict__ p, float r[8]) {
    asm volatile(
        "ld.global.cs.v8.f32 {%0,%1,%2,%3,%4,%5,%6,%7}, [%8];"
        : "=f"(r[0]), "=f"(r[1]), "=f"(r[2]), "=f"(r[3]),
          "=f"(r[4]), "=f"(r[5]), "=f"(r[6]), "=f"(r[7])
        : "l"(p));
}

__global__ __launch_bounds__(NTHREADS) void dot_loss_kernel(
    const float* __restrict__ fs, const float* __restrict__ ft,
    float* __restrict__ out, int n8, float neg_inv_b) {
    float acc0 = 0.0f, acc1 = 0.0f;
    int i = blockIdx.x * NTHREADS + threadIdx.x;   // float8 index
    const int stride = NBLOCKS * NTHREADS;

    float a0[8], a1[8], b0[8], b1[8];

    // Unroll 2: four LDG.256 front-batched => 128B in flight per thread
    #pragma unroll 1
    for (; i + stride < n8; i += 2 * stride) {
        ldg256_cs(fs + (size_t)i * 8, a0);
        ldg256_cs(fs + (size_t)(i + stride) * 8, a1);
        ldg256_cs(ft + (size_t)i * 8, b0);
        ldg256_cs(ft + (size_t)(i + stride) * 8, b1);
        #pragma unroll
        for (int k = 0; k < 8; k++) acc0 = fmaf(a0[k], b0[k], acc0);
        #pragma unroll
        for (int k = 0; k < 8; k++) acc1 = fmaf(a1[k], b1[k], acc1);
    }
    for (; i < n8; i += stride) {
        ldg256_cs(fs + (size_t)i * 8, a0);
        ldg256_cs(ft + (size_t)i * 8, b0);
        #pragma unroll
        for (int k = 0; k < 8; k++) acc0 = fmaf(a0[k], b0[k], acc0);
    }
    float acc = acc0 + acc1;

    // warp reduce
    #pragma unroll
    for (int off = 16; off > 0; off >>= 1)
        acc += __shfl_xor_sync(0xFFFFFFFFu, acc, off);

    __shared__ float s[NTHREADS / 32];
    int lane = threadIdx.x & 31;
    int wid = threadIdx.x >> 5;
    if (lane == 0) s[wid] = acc;
    __syncthreads();

    if (threadIdx.x == 0) {
        float v = 0.0f;
        #pragma unroll
        for (int w = 0; w < NTHREADS / 32; w++) v += s[w];

        // exact, order-independent accumulation: fixed-point int64
        long long fp = (long long)((double)v * FP_SCALE);
        atomicAdd(&g_sum, (unsigned long long)fp);
        __threadfence();
        unsigned int t = atomicAdd(&g_ticket, 1u);
        if (t == NBLOCKS - 1) {
            unsigned long long total_u = atomicAdd(&g_sum, 0ull);  // atomic read
            long long total = (long long)total_u;
            double sum = (double)total * (1.0 / FP_SCALE);
            out[0] = (float)(sum * (double)neg_inv_b);
            g_sum = 0ull;      // reset for next graph replay
            g_ticket = 0;
            __threadfence();
        }
    }
}

extern "C" void kernel_launch(void* const* d_in, const int* in_sizes, int n_in,
                              void* d_out, int out_size) {
    const float* fs = (const float*)d_in[0];
    const float* ft = (const float*)d_in[1];
    float* out = (float*)d_out;

    int n = in_sizes[0];   // B * D floats
    int n8 = n >> 3;       // float8 count

    int B = n / 512;       // D = 512
    float neg_inv_b = -1.0f / (float)B;

    dot_loss_kernel<<<NBLOCKS, NTHREADS>>>(fs, ft, out, n8, neg_inv_b);
}